// round 9
// baseline (speedup 1.0000x reference)
#include <cuda_runtime.h>
#include <cstdint>

// Depthwise1d: out[n,c,o] = sum_i x[n,c,i] * W[c,o,i] + b[c,o]
// N=4096, C=256, K=64, O=128, fp32.
//
// R8 (= R7 re-bench after infra failure): persistent CTAs (304 = 2/SM),
// contiguous channel-major tile chunks (W amortized), X double-buffered with
// cp.async so staging hides behind compute. Compute tile: col-pair FFMA2,
// r=8 x c=8 (the calibrated 1:1 L1-wf : fma-cycle tile).

#define N_TOT   4096
#define C_TOT   256
#define K_IN    64
#define O_OUT   128
#define TILE_M  128
#define THREADS 256
#define XSTR    68
#define WSTR    132
#define XBUF_FL (TILE_M * XSTR)          // 8704 floats per X buffer
#define NCTAS   304
#define NTILES  (N_TOT / TILE_M * C_TOT) // 8192, channel-major: tile>>5 = c

// 8 MB scratch: W2g[c][k][o]
__device__ float W2g[C_TOT * K_IN * O_OUT];

__device__ __forceinline__ void ffma2(unsigned long long& d,
                                      unsigned long long a,
                                      unsigned long long b) {
    asm("fma.rn.f32x2 %0, %1, %2, %0;" : "+l"(d) : "l"(a), "l"(b));
}
__device__ __forceinline__ unsigned long long dup2(float w) {
    unsigned long long r;
    asm("mov.b64 %0, {%1, %1};" : "=l"(r) : "f"(w));
    return r;
}
__device__ __forceinline__ float2 unpack2(unsigned long long v) {
    float2 f;
    asm("mov.b64 {%0, %1}, %2;" : "=f"(f.x), "=f"(f.y) : "l"(v));
    return f;
}
__device__ __forceinline__ uint32_t smem_u32(const void* p) {
    uint32_t a;
    asm("{ .reg .u64 t; cvta.to.shared.u64 t, %1; cvt.u32.u64 %0, t; }" : "=r"(a) : "l"(p));
    return a;
}
__device__ __forceinline__ void cp_async16(uint32_t dst, const void* src) {
    asm volatile("cp.async.cg.shared.global [%0], [%1], 16;" :: "r"(dst), "l"(src));
}
#define CP_COMMIT() asm volatile("cp.async.commit_group;" ::: "memory")
#define CP_WAIT0()  asm volatile("cp.async.wait_group 0;" ::: "memory")

// ---- Kernel A: W[c][o][k] -> W2g[c][k][o] ----
__global__ __launch_bounds__(256)
void w_transpose(const float* __restrict__ W) {
    __shared__ float Wt[O_OUT * 68];
    const int t = threadIdx.x;
    const int c = blockIdx.x;
#pragma unroll
    for (int j = 0; j < 8; ++j) {
        int idx = t + 256 * j;
        int o = idx >> 4, q = idx & 15;
        float4 v = *(const float4*)(W + ((size_t)c * O_OUT + o) * K_IN + 4 * q);
        *(float4*)&Wt[o * 68 + 4 * q] = v;
    }
    __syncthreads();
    float* dst = W2g + (size_t)c * K_IN * O_OUT;
#pragma unroll
    for (int j = 0; j < 32; ++j) {
        int idx = t + 256 * j;
        int k = idx >> 7, o = idx & 127;
        dst[k * O_OUT + o] = Wt[o * 68 + k];
    }
}

// X prefetch for one tile into buffer bufsel (cp.async, 8 x 16B per thread)
__device__ __forceinline__ void prefetch_x(const float* __restrict__ x,
                                           uint32_t smem_base_u32,
                                           int tile, int bufsel, int t) {
    const int c  = tile >> 5;
    const int m0 = (tile & 31) << 7;
    const float* xb = x + (size_t)c * K_IN;
    uint32_t sbase = smem_base_u32 + (uint32_t)(bufsel * XBUF_FL * 4);
#pragma unroll
    for (int j = 0; j < 8; ++j) {
        int idx = t + THREADS * j;              // 0..2047
        int row = idx >> 4, ku = idx & 15;
        const void* src = xb + (size_t)(m0 + row) * C_TOT * K_IN + 4 * ku;
        cp_async16(sbase + (uint32_t)((row * XSTR + 4 * ku) * 4), src);
    }
}

// ---- Kernel B: persistent main GEMM ----
__global__ __launch_bounds__(THREADS, 2)
void dw1d_persist(const float* __restrict__ x,
                  const float* __restrict__ b,
                  float* __restrict__ out) {
    extern __shared__ float smem[];
    float* Wsh = smem + 2 * XBUF_FL;            // [k][o] stride WSTR

    const int t  = threadIdx.x;
    const int cg = t & 15;
    const int rg = t >> 4;
    const uint32_t sb32 = smem_u32(smem);

    // contiguous chunk assignment: 8192 tiles over 304 CTAs
    const int bid   = blockIdx.x;
    const int base  = NTILES / NCTAS;                 // 26
    const int rem   = NTILES - base * NCTAS;          // 288
    const int cnt   = base + (bid < rem ? 1 : 0);
    const int start = bid * base + (bid < rem ? bid : rem);

    int cur_c = -1;
    int buf = 0;

    if (cnt > 0) {
        prefetch_x(x, sb32, start, 0, t);
        CP_COMMIT();
    }

    for (int ii = 0; ii < cnt; ++ii) {
        const int tile = start + ii;
        const int c  = tile >> 5;
        const int m0 = (tile & 31) << 7;

        CP_WAIT0();
        __syncthreads();                            // X(tile) visible to all

        if (ii + 1 < cnt) {                         // prefetch next X
            prefetch_x(x, sb32, tile + 1, buf ^ 1, t);
            CP_COMMIT();
        }

        if (c != cur_c) {                           // (re)stage W for channel
            const float* wb = W2g + (size_t)c * K_IN * O_OUT;
#pragma unroll
            for (int j = 0; j < 8; ++j) {
                int idx = t + THREADS * j;
                int k = idx >> 5, o4 = idx & 31;
                float4 v = *(const float4*)(wb + k * O_OUT + 4 * o4);
                *(float4*)&Wsh[k * WSTR + 4 * o4] = v;
            }
            cur_c = c;
            __syncthreads();
        }

        // ---- compute from Xsh = smem + buf*XBUF_FL ----
        const float* Xsh = smem + buf * XBUF_FL;
        unsigned long long acc[8][4];
#pragma unroll
        for (int i = 0; i < 8; ++i)
#pragma unroll
            for (int j = 0; j < 4; ++j)
                acc[i][j] = 0ULL;

        const float* wrow0 = &Wsh[4 * cg];
        const float* wrow1 = &Wsh[4 * cg + 64];

#pragma unroll 4
        for (int k = 0; k < K_IN; ++k) {
            float xs[8];
#pragma unroll
            for (int i = 0; i < 8; ++i)
                xs[i] = Xsh[(rg + 16 * i) * XSTR + k];

            ulonglong2 wv0 = *(const ulonglong2*)(wrow0 + k * WSTR);
            ulonglong2 wv1 = *(const ulonglong2*)(wrow1 + k * WSTR);
#pragma unroll
            for (int i = 0; i < 8; ++i) {
                unsigned long long xd = dup2(xs[i]);
                ffma2(acc[i][0], xd, wv0.x);
                ffma2(acc[i][1], xd, wv0.y);
                ffma2(acc[i][2], xd, wv1.x);
                ffma2(acc[i][3], xd, wv1.y);
            }
        }

        // ---- epilogue: bias from global (L2-hot), 2 STG.128 per row ----
        const float4 b0 = __ldg((const float4*)(b + c * O_OUT + 4 * cg));
        const float4 b1 = __ldg((const float4*)(b + c * O_OUT + 64 + 4 * cg));

#pragma unroll
        for (int i = 0; i < 8; ++i) {
            int n = m0 + rg + 16 * i;
            float* orow = out + ((size_t)n * C_TOT + c) * O_OUT;
            float2 p0 = unpack2(acc[i][0]);
            float2 p1 = unpack2(acc[i][1]);
            float2 p2 = unpack2(acc[i][2]);
            float2 p3 = unpack2(acc[i][3]);
            float4 v0 = make_float4(p0.x + b0.x, p0.y + b0.y, p1.x + b0.z, p1.y + b0.w);
            float4 v1 = make_float4(p2.x + b1.x, p2.y + b1.y, p3.x + b1.z, p3.y + b1.w);
            *(float4*)&orow[4 * cg]      = v0;
            *(float4*)&orow[64 + 4 * cg] = v1;
        }

        buf ^= 1;
    }
}

extern "C" void kernel_launch(void* const* d_in, const int* in_sizes, int n_in,
                              void* d_out, int out_size) {
    const float* x = (const float*)d_in[0];
    const float* W = (const float*)d_in[1];
    const float* b = (const float*)d_in[2];
    float* out = (float*)d_out;

    w_transpose<<<C_TOT, 256>>>(W);

    size_t smem_bytes = (size_t)(2 * XBUF_FL + K_IN * WSTR) * sizeof(float); // 103424
    cudaFuncSetAttribute(dw1d_persist,
                         cudaFuncAttributeMaxDynamicSharedMemorySize,
                         (int)smem_bytes);
    dw1d_persist<<<NCTAS, THREADS, smem_bytes>>>(x, b, out);
}

// round 10
// speedup vs baseline: 1.9123x; 1.9123x over previous
#include <cuda_runtime.h>
#include <cstdint>

// Depthwise1d: out[n,c,o] = sum_i x[n,c,i] * W[c,o,i] + b[c,o]
// N=4096, C=256, K=64, O=128, fp32.
//
// R9: R6 skeleton (fresh CTA per 128x128 tile, W pre-transposed k-major by
// helper kernel) + k-pair x loads (LDS.64 instead of 2x LDS.32 broadcast)
// to cut compute-phase L1 wavefronts ~25%. Col-pair FFMA2, r=8 x c=8.

#define N_TOT   4096
#define C_TOT   256
#define K_IN    64
#define O_OUT   128
#define TILE_M  128
#define THREADS 256
#define XSTR    68       // Xsh row stride (floats)
#define WSTR    132      // Wsh k-row stride (floats)

// 8 MB scratch: W2g[c][k][o]
__device__ float W2g[C_TOT * K_IN * O_OUT];

__device__ __forceinline__ void ffma2(unsigned long long& d,
                                      unsigned long long a,
                                      unsigned long long b) {
    asm("fma.rn.f32x2 %0, %1, %2, %0;" : "+l"(d) : "l"(a), "l"(b));
}
__device__ __forceinline__ unsigned long long dup2(float w) {
    unsigned long long r;
    asm("mov.b64 %0, {%1, %1};" : "=l"(r) : "f"(w));
    return r;
}
__device__ __forceinline__ float2 unpack2(unsigned long long v) {
    float2 f;
    asm("mov.b64 {%0, %1}, %2;" : "=f"(f.x), "=f"(f.y) : "l"(v));
    return f;
}

// ---- Kernel A: W[c][o][k] -> W2g[c][k][o] (tiny) ----
__global__ __launch_bounds__(256)
void w_transpose(const float* __restrict__ W) {
    __shared__ float Wt[O_OUT * 68];
    const int t = threadIdx.x;
    const int c = blockIdx.x;
#pragma unroll
    for (int j = 0; j < 8; ++j) {
        int idx = t + 256 * j;
        int o = idx >> 4, q = idx & 15;
        float4 v = *(const float4*)(W + ((size_t)c * O_OUT + o) * K_IN + 4 * q);
        *(float4*)&Wt[o * 68 + 4 * q] = v;
    }
    __syncthreads();
    float* dst = W2g + (size_t)c * K_IN * O_OUT;
#pragma unroll
    for (int j = 0; j < 32; ++j) {
        int idx = t + 256 * j;
        int k = idx >> 7, o = idx & 127;
        dst[k * O_OUT + o] = Wt[o * 68 + k];
    }
}

// ---- Kernel B: main GEMM ----
__global__ __launch_bounds__(THREADS, 2)
void dw1d_kernel(const float* __restrict__ x,
                 const float* __restrict__ b,
                 float* __restrict__ out) {
    extern __shared__ float smem[];
    float* Xsh = smem;                       // [row][k] stride XSTR
    float* Wsh = smem + TILE_M * XSTR;       // [k][o]   stride WSTR

    const int t  = threadIdx.x;
    const int cg = t & 15;
    const int rg = t >> 4;
    const int n0 = blockIdx.x * TILE_M;
    const int c  = blockIdx.y;

    // stage x: coalesced LDG.128 -> Xsh[row][k]
    {
        const float* xb = x + (size_t)c * K_IN;
#pragma unroll
        for (int j = 0; j < 8; ++j) {
            int idx = t + THREADS * j;       // 0..2047
            int row = idx >> 4, ku = idx & 15;
            float4 v = *(const float4*)(xb + (size_t)(n0 + row) * C_TOT * K_IN + 4 * ku);
            *(float4*)&Xsh[row * XSTR + 4 * ku] = v;
        }
    }
    // stage W (k-major): coalesced LDG.128 -> Wsh[k][o]
    {
        const float* wb = W2g + (size_t)c * K_IN * O_OUT;
#pragma unroll
        for (int j = 0; j < 8; ++j) {
            int idx = t + THREADS * j;       // 0..2047
            int k = idx >> 5, o4 = idx & 31;
            float4 v = *(const float4*)(wb + k * O_OUT + 4 * o4);
            *(float4*)&Wsh[k * WSTR + 4 * o4] = v;
        }
    }
    __syncthreads();

    // compute: rows r_i = rg + 16*i (i<8); cols {4cg..+3, 64+4cg..+3}
    unsigned long long acc[8][4];
#pragma unroll
    for (int i = 0; i < 8; ++i)
#pragma unroll
        for (int j = 0; j < 4; ++j)
            acc[i][j] = 0ULL;

    const float* wrow0 = &Wsh[4 * cg];
    const float* wrow1 = &Wsh[4 * cg + 64];

#pragma unroll 4
    for (int k2 = 0; k2 < K_IN / 2; ++k2) {
        // x: one LDS.64 per row fetches k-pair (x[2k2], x[2k2+1])
        unsigned long long xp[8];
#pragma unroll
        for (int i = 0; i < 8; ++i)
            xp[i] = *(const unsigned long long*)&Xsh[(rg + 16 * i) * XSTR + 2 * k2];

        // W rows for k = 2k2 and 2k2+1
        ulonglong2 wa0 = *(const ulonglong2*)(wrow0 + (2 * k2) * WSTR);
        ulonglong2 wa1 = *(const ulonglong2*)(wrow1 + (2 * k2) * WSTR);
        ulonglong2 wb0 = *(const ulonglong2*)(wrow0 + (2 * k2 + 1) * WSTR);
        ulonglong2 wb1 = *(const ulonglong2*)(wrow1 + (2 * k2 + 1) * WSTR);

#pragma unroll
        for (int i = 0; i < 8; ++i) {
            float2 xf = unpack2(xp[i]);
            unsigned long long x0 = dup2(xf.x);
            unsigned long long x1 = dup2(xf.y);
            ffma2(acc[i][0], x0, wa0.x);
            ffma2(acc[i][1], x0, wa0.y);
            ffma2(acc[i][2], x0, wa1.x);
            ffma2(acc[i][3], x0, wa1.y);
            ffma2(acc[i][0], x1, wb0.x);
            ffma2(acc[i][1], x1, wb0.y);
            ffma2(acc[i][2], x1, wb1.x);
            ffma2(acc[i][3], x1, wb1.y);
        }
    }

    // epilogue: bias via __ldg (L2-hot), 2 coalesced STG.128 per row
    const float4 b0 = __ldg((const float4*)(b + c * O_OUT + 4 * cg));
    const float4 b1 = __ldg((const float4*)(b + c * O_OUT + 64 + 4 * cg));

#pragma unroll
    for (int i = 0; i < 8; ++i) {
        int n = n0 + rg + 16 * i;
        float* orow = out + ((size_t)n * C_TOT + c) * O_OUT;
        float2 p0 = unpack2(acc[i][0]);
        float2 p1 = unpack2(acc[i][1]);
        float2 p2 = unpack2(acc[i][2]);
        float2 p3 = unpack2(acc[i][3]);
        float4 v0 = make_float4(p0.x + b0.x, p0.y + b0.y, p1.x + b0.z, p1.y + b0.w);
        float4 v1 = make_float4(p2.x + b1.x, p2.y + b1.y, p3.x + b1.z, p3.y + b1.w);
        *(float4*)&orow[4 * cg]      = v0;
        *(float4*)&orow[64 + 4 * cg] = v1;
    }
}

extern "C" void kernel_launch(void* const* d_in, const int* in_sizes, int n_in,
                              void* d_out, int out_size) {
    const float* x = (const float*)d_in[0];
    const float* W = (const float*)d_in[1];
    const float* b = (const float*)d_in[2];
    float* out = (float*)d_out;

    w_transpose<<<C_TOT, 256>>>(W);

    size_t smem_bytes = (size_t)(TILE_M * XSTR + K_IN * WSTR) * sizeof(float); // 68608
    cudaFuncSetAttribute(dw1d_kernel,
                         cudaFuncAttributeMaxDynamicSharedMemorySize,
                         (int)smem_bytes);
    dim3 grid(N_TOT / TILE_M, C_TOT);
    dw1d_kernel<<<grid, THREADS, smem_bytes>>>(x, b, out);
}